// round 2
// baseline (speedup 1.0000x reference)
#include <cuda_runtime.h>
#include <cstdint>

typedef unsigned long long ull;

#define NB 16
#define NOVER 7168
#define NP 1024
#define NIMP 768
#define NCOV 256
#define REND_ELEMS (NB*7*NP)   /* 114688 */

// ---------------- packed f32x2 helpers ----------------
__device__ __forceinline__ ull pack2(float lo, float hi){
  ull r;
  asm("mov.b64 %0, {%1, %2};" : "=l"(r) : "r"(__float_as_uint(lo)), "r"(__float_as_uint(hi)));
  return r;
}
__device__ __forceinline__ void unpack2(ull v, float& lo, float& hi){
  unsigned a, b;
  asm("mov.b64 {%0, %1}, %2;" : "=r"(a), "=r"(b) : "l"(v));
  lo = __uint_as_float(a); hi = __uint_as_float(b);
}
__device__ __forceinline__ ull fma2(ull a, ull b, ull c){
  ull d;
  asm("fma.rn.f32x2 %0, %1, %2, %3;" : "=l"(d) : "l"(a), "l"(b), "l"(c));
  return d;
}

// ---------------- bilinear sample (feeds MLP; tolerance-level only) -------
__device__ __forceinline__ float bil(const float* __restrict__ base, int W, int H,
                                     float px, float py){
  float gx = 2.f*px - 1.f, gy = 2.f*py - 1.f;
  float x = ((gx + 1.f)*(float)W - 1.f)*0.5f;
  float y = ((gy + 1.f)*(float)H - 1.f)*0.5f;
  float x0f = floorf(x), y0f = floorf(y);
  float wx = x - x0f, wy = y - y0f;
  int x0 = (int)x0f, y0 = (int)y0f, x1 = x0 + 1, y1 = y0 + 1;
  bool vx0 = (x0 >= 0) && (x0 < W), vx1 = (x1 >= 0) && (x1 < W);
  bool vy0 = (y0 >= 0) && (y0 < H), vy1 = (y1 >= 0) && (y1 < H);
  float v00 = (vx0 && vy0) ? base[y0*W + x0] : 0.f;
  float v01 = (vx1 && vy0) ? base[y0*W + x1] : 0.f;
  float v10 = (vx0 && vy1) ? base[y1*W + x0] : 0.f;
  float v11 = (vx1 && vy1) ? base[y1*W + x1] : 0.f;
  return v00*(1.f-wx)*(1.f-wy) + v01*wx*(1.f-wy) + v10*(1.f-wx)*wy + v11*wx*wy;
}

// =========================================================================
// Kernel 1: per batch -> top2 maps -> uncertainty (BITWISE-matching the
// reference's eager f32 op sequence) -> exact top-768 via radix select ->
// bitonic sort of 1024 -> points written into d_out
// =========================================================================
__global__ __launch_bounds__(1024) void k2_points(
    const float* __restrict__ coarse, const float* __restrict__ over_gen,
    const float* __restrict__ coverage, float* __restrict__ out)
{
  extern __shared__ char sm[];
  float* m1s = (float*)sm;                       // 4096 f
  float* m2s = m1s + 4096;                       // 4096 f
  ull*   keys = (ull*)(sm + 32768);              // 7168 u64
  ull*   sel  = (ull*)(sm + 32768 + 57344);      // 1024 u64
  unsigned* cum  = (unsigned*)(sm + 98304);      // 256
  unsigned* misc = cum + 256;                    // [0]=krem [1]=digit [2]=below [3]=cnt
  ull* s_pfx = (ull*)(misc + 4);

  const int b = blockIdx.x, tid = threadIdx.x;
  const float NEG_INF = __int_as_float(0xff800000);

  // per-pixel top-2 of 7 coarse channels (== channels 0,1 of sorted coarse)
  const float* cb = coarse + (size_t)b*7*4096;
  for (int l = tid; l < 4096; l += 1024){
    float m1 = NEG_INF, m2 = NEG_INF;
    #pragma unroll
    for (int c = 0; c < 7; c++){
      float v = cb[c*4096 + l];
      if (v > m1){ m2 = m1; m1 = v; } else if (v > m2) m2 = v;
    }
    m1s[l] = m1; m2s[l] = m2;
  }
  if (tid == 0){ *s_pfx = 0ull; misc[0] = NIMP; misc[3] = 0; }
  __syncthreads();

  // uncertainty for 7168 points, strictly replicating reference rounding:
  //   gx = 2*p - 1 ; x = ((gx+1)*W - 1)*0.5 ; wx = x - floor(x)
  //   samp = ((v*(1-wx))*(1-wy)) + ((v*wx)*(1-wy)) + ((v*(1-wx))*wy) + ((v*wx)*wy)
  //   (left-assoc sum, every intermediate rounded f32, masked corners = 0)
  const float* og = over_gen + (size_t)b*NOVER*2;
  for (int t = 0; t < 7; t++){
    int i = tid + t*1024;
    float px = og[i*2], py = og[i*2 + 1];
    float gx = __fsub_rn(__fmul_rn(2.f, px), 1.f);
    float gy = __fsub_rn(__fmul_rn(2.f, py), 1.f);
    float x  = __fmul_rn(__fsub_rn(__fmul_rn(__fadd_rn(gx, 1.f), 64.f), 1.f), 0.5f);
    float y  = __fmul_rn(__fsub_rn(__fmul_rn(__fadd_rn(gy, 1.f), 64.f), 1.f), 0.5f);
    float x0f = floorf(x), y0f = floorf(y);
    float wx = __fsub_rn(x, x0f), wy = __fsub_rn(y, y0f);
    float omx = __fsub_rn(1.f, wx), omy = __fsub_rn(1.f, wy);
    float x1f = __fadd_rn(x0f, 1.f), y1f = __fadd_rn(y0f, 1.f);
    bool vx0 = (x0f >= 0.f) && (x0f <= 63.f);
    bool vx1 = (x1f >= 0.f) && (x1f <= 63.f);
    bool vy0 = (y0f >= 0.f) && (y0f <= 63.f);
    bool vy1 = (y1f >= 0.f) && (y1f <= 63.f);
    int ix0 = min(max((int)x0f, 0), 63), iy0 = min(max((int)y0f, 0), 63);
    int ix1 = min(max((int)x1f, 0), 63), iy1 = min(max((int)y1f, 0), 63);
    int o00 = iy0*64 + ix0, o01 = iy0*64 + ix1, o10 = iy1*64 + ix0, o11 = iy1*64 + ix1;
    float a00 = (vx0 && vy0) ? m1s[o00] : 0.f;
    float a01 = (vx1 && vy0) ? m1s[o01] : 0.f;
    float a10 = (vx0 && vy1) ? m1s[o10] : 0.f;
    float a11 = (vx1 && vy1) ? m1s[o11] : 0.f;
    float b00 = (vx0 && vy0) ? m2s[o00] : 0.f;
    float b01 = (vx1 && vy0) ? m2s[o01] : 0.f;
    float b10 = (vx0 && vy1) ? m2s[o10] : 0.f;
    float b11 = (vx1 && vy1) ? m2s[o11] : 0.f;
    float s0 = __fadd_rn(__fadd_rn(__fadd_rn(
                 __fmul_rn(__fmul_rn(a00, omx), omy),
                 __fmul_rn(__fmul_rn(a01, wx ), omy)),
                 __fmul_rn(__fmul_rn(a10, omx), wy )),
                 __fmul_rn(__fmul_rn(a11, wx ), wy ));
    float s1 = __fadd_rn(__fadd_rn(__fadd_rn(
                 __fmul_rn(__fmul_rn(b00, omx), omy),
                 __fmul_rn(__fmul_rn(b01, wx ), omy)),
                 __fmul_rn(__fmul_rn(b10, omx), wy )),
                 __fmul_rn(__fmul_rn(b11, wx ), wy ));
    float unc = __fsub_rn(s1, s0);             // == -(s0 - s1) bitwise
    unsigned u = __float_as_uint(unc);
    unsigned mo = (u & 0x80000000u) ? ~u : (u | 0x80000000u); // order-preserving
    unsigned kv = ~mo;                         // ascending kv == descending unc
    keys[i] = ((ull)kv << 13) | (unsigned)i;   // tie-break: ascending index
  }
  __syncthreads();

  // radix select: 768th-smallest 45-bit key (keys unique -> no tie logic)
  for (int r = 0; r < 6; r++){
    if (tid < 256) cum[tid] = 0;
    __syncthreads();
    ull pfx = *s_pfx; unsigned krem = misc[0];
    int shift = 40 - 8*r;
    for (int t = 0; t < 7; t++){
      ull key = keys[tid + t*1024];
      if ((key >> (shift + 8)) == pfx)
        atomicAdd(&cum[(unsigned)(key >> shift) & 255u], 1u);
    }
    __syncthreads();
    for (int off = 1; off < 256; off <<= 1){
      unsigned v = 0;
      if (tid < 256 && tid >= off) v = cum[tid - off];
      __syncthreads();
      if (tid < 256) cum[tid] += v;
      __syncthreads();
    }
    if (tid < 256){
      unsigned le = cum[tid];
      unsigned lt = tid ? cum[tid - 1] : 0u;
      if (le >= krem && lt < krem){ misc[1] = tid; misc[2] = lt; }
    }
    __syncthreads();
    if (tid == 0){ *s_pfx = (*s_pfx << 8) | (ull)misc[1]; misc[0] -= misc[2]; }
    __syncthreads();
  }
  ull T = *s_pfx;            // exact 768th-smallest key

  // compact the 768 selected keys (unordered), then sort 1024 bitonically
  for (int t = 0; t < 7; t++){
    ull key = keys[tid + t*1024];
    if (key <= T){
      unsigned pos = atomicAdd(&misc[3], 1u);
      if (pos < 1024) sel[pos] = key;
    }
  }
  __syncthreads();
  if (tid >= NIMP) sel[tid] = ~0ull;
  __syncthreads();
  for (int k = 2; k <= 1024; k <<= 1){
    for (int j = k >> 1; j > 0; j >>= 1){
      int ixj = tid ^ j;
      if (ixj > tid){
        ull a = sel[tid], bb = sel[ixj];
        bool up = ((tid & k) == 0);
        if ((a > bb) == up){ sel[tid] = bb; sel[ixj] = a; }
      }
      __syncthreads();
    }
  }

  // points = concat(importance, coverage)  -> points region of d_out
  float px, py;
  if (tid < NIMP){
    int idx = (int)(sel[tid] & 0x1FFFu);
    px = og[idx*2]; py = og[idx*2 + 1];
  } else {
    int j = tid - NIMP;
    px = coverage[((size_t)b*NCOV + j)*2];
    py = coverage[((size_t)b*NCOV + j)*2 + 1];
  }
  float* op = out + REND_ELEMS + ((size_t)b*NP + tid)*2;
  op[0] = px; op[1] = py;
}

// =========================================================================
// Kernel 2: gather coarse+fine feats at points, MLP (135->256 relu ->7),
// write rend. 128 blocks (b, chunk of 128 points), 512 threads.
// =========================================================================
__global__ __launch_bounds__(512) void k3_head(
    const float* __restrict__ coarse, const float* __restrict__ fine,
    const float* __restrict__ w1, const float* __restrict__ b1,
    const float* __restrict__ w2, const float* __restrict__ b2,
    float* __restrict__ out)
{
  extern __shared__ float sf[];
  float* fs  = sf;                    // 128*136
  float* wsh = fs + 128*136;          // 16*256
  float* w2s = wsh + 4096;            // 256*7
  float* ps  = w2s + 1792;            // 128*2
  float* hs  = ps + 256;              // 128*258

  const int b = blockIdx.y, chunk = blockIdx.x;
  const int tid = threadIdx.x;
  const int pbase = chunk*128;

  const float* pts_g = out + REND_ELEMS + ((size_t)b*NP + pbase)*2;
  for (int i = tid; i < 256;  i += 512) ps[i]  = pts_g[i];
  for (int i = tid; i < 1792; i += 512) w2s[i] = w2[i];
  __syncthreads();

  // gather feat[pt][c]: c<7 coarse (64x64), c>=7 fine channel c-7 (256x256)
  const float* cbase = coarse + (size_t)b*7*4096;
  const float* fbase = fine + (size_t)b*128*65536;
  for (int t = tid; t < 128*135; t += 512){
    int pt = t / 135;
    int c  = t - pt*135;
    float px = ps[pt*2], py = ps[pt*2 + 1];
    float val;
    if (c < 7) val = bil(cbase + c*4096, 64, 64, px, py);
    else       val = bil(fbase + (size_t)(c - 7)*65536, 256, 256, px, py);
    fs[pt*136 + c] = val;
  }

  // GEMM1: h = relu(feat @ w1 + b1), packed f32x2, 8pt x 8col per thread.
  const int colg = tid & 31, ptg = tid >> 5;
  const int p0 = ptg*8;
  ull acc[8][4];
  {
    ull binit[4];
    #pragma unroll
    for (int q = 0; q < 4; q++){
      int c0 = 2*colg + 64*q;
      binit[q] = pack2(b1[c0], b1[c0 + 1]);
    }
    #pragma unroll
    for (int p = 0; p < 8; p++)
      #pragma unroll
      for (int q = 0; q < 4; q++) acc[p][q] = binit[q];
  }
  for (int k0 = 0; k0 < 135; k0 += 16){
    int kc = min(16, 135 - k0);
    __syncthreads();                               // also covers gather->read
    for (int i = tid; i < kc*256; i += 512) wsh[i] = w1[k0*256 + i];
    __syncthreads();
    for (int r = 0; r < kc; r++){
      const ull* wrow = (const ull*)(wsh + r*256);
      ull wv0 = wrow[colg], wv1 = wrow[colg + 32], wv2 = wrow[colg + 64], wv3 = wrow[colg + 96];
      const float* fcol = fs + (k0 + r);
      #pragma unroll
      for (int p = 0; p < 8; p++){
        float fv = fcol[(p0 + p)*136];
        ull ff = pack2(fv, fv);
        acc[p][0] = fma2(ff, wv0, acc[p][0]);
        acc[p][1] = fma2(ff, wv1, acc[p][1]);
        acc[p][2] = fma2(ff, wv2, acc[p][2]);
        acc[p][3] = fma2(ff, wv3, acc[p][3]);
      }
    }
  }

  // relu -> hs
  #pragma unroll
  for (int p = 0; p < 8; p++){
    #pragma unroll
    for (int q = 0; q < 4; q++){
      float lo, hi; unpack2(acc[p][q], lo, hi);
      int c0 = 2*colg + 64*q;
      hs[(p0 + p)*258 + c0]     = fmaxf(lo, 0.f);
      hs[(p0 + p)*258 + c0 + 1] = fmaxf(hi, 0.f);
    }
  }
  __syncthreads();

  // GEMM2: rend[b][cls][n] = h @ w2 + b2
  for (int t = tid; t < 896; t += 512){
    int pt = t / 7, cls = t - pt*7;
    const float* hrow = hs + pt*258;
    float s = b2[cls];
    #pragma unroll 8
    for (int k = 0; k < 256; k++) s = fmaf(hrow[k], w2s[k*7 + cls], s);
    out[((size_t)b*7 + cls)*NP + pbase + pt] = s;
  }
}

// =========================================================================
extern "C" void kernel_launch(void* const* d_in, const int* in_sizes, int n_in,
                              void* d_out, int out_size){
  const float *fine = nullptr, *coarse = nullptr, *w1 = nullptr, *b1 = nullptr,
              *w2 = nullptr, *b2 = nullptr, *og = nullptr, *cov = nullptr;
  for (int i = 0; i < n_in; i++){
    switch (in_sizes[i]){
      case 134217728: fine   = (const float*)d_in[i]; break;
      case 458752:    coarse = (const float*)d_in[i]; break;
      case 34560:     w1     = (const float*)d_in[i]; break;
      case 256:       b1     = (const float*)d_in[i]; break;
      case 1792:      w2     = (const float*)d_in[i]; break;
      case 7:         b2     = (const float*)d_in[i]; break;
      case 229376:    og     = (const float*)d_in[i]; break;
      case 8192:      cov    = (const float*)d_in[i]; break;
      default: break;
    }
  }
  float* out = (float*)d_out;

  const size_t sm2 = 100352;
  const size_t sm3 = (size_t)(128*136 + 4096 + 1792 + 256 + 128*258)*sizeof(float); // 226304
  cudaFuncSetAttribute(k2_points, cudaFuncAttributeMaxDynamicSharedMemorySize, (int)sm2);
  cudaFuncSetAttribute(k3_head,   cudaFuncAttributeMaxDynamicSharedMemorySize, (int)sm3);

  k2_points<<<NB, 1024, sm2>>>(coarse, og, cov, out);
  k3_head<<<dim3(8, NB), 512, sm3>>>(coarse, fine, w1, b1, w2, b2, out);
}

// round 4
// speedup vs baseline: 1.5132x; 1.5132x over previous
#include <cuda_runtime.h>
#include <cstdint>

typedef unsigned long long ull;

#define NB 16
#define NOVER 7168
#define NP 1024
#define NIMP 768
#define NCOV 256
#define REND_ELEMS (NB*7*NP)   /* 114688 */
#define NCH 135
#define FPITCH 136
#define GITEMS (NB*NP*NCH)     /* 2211840 */

// feat scratch: [b][pt][c], c-contiguous, padded to 136
__device__ float g_feat[(size_t)NB*NP*FPITCH];

// ---------------- packed f32x2 helpers ----------------
__device__ __forceinline__ ull pack2(float lo, float hi){
  ull r;
  asm("mov.b64 %0, {%1, %2};" : "=l"(r) : "r"(__float_as_uint(lo)), "r"(__float_as_uint(hi)));
  return r;
}
__device__ __forceinline__ void unpack2(ull v, float& lo, float& hi){
  unsigned a, b;
  asm("mov.b64 {%0, %1}, %2;" : "=r"(a), "=r"(b) : "l"(v));
  lo = __uint_as_float(a); hi = __uint_as_float(b);
}
__device__ __forceinline__ ull fma2(ull a, ull b, ull c){
  ull d;
  asm("fma.rn.f32x2 %0, %1, %2, %3;" : "=l"(d) : "l"(a), "l"(b), "l"(c));
  return d;
}

// ---------------- bilinear sample (feeds MLP; tolerance-level only) -------
__device__ __forceinline__ float bil(const float* __restrict__ base, int W, int H,
                                     float px, float py){
  float gx = 2.f*px - 1.f, gy = 2.f*py - 1.f;
  float x = ((gx + 1.f)*(float)W - 1.f)*0.5f;
  float y = ((gy + 1.f)*(float)H - 1.f)*0.5f;
  float x0f = floorf(x), y0f = floorf(y);
  float wx = x - x0f, wy = y - y0f;
  int x0 = (int)x0f, y0 = (int)y0f, x1 = x0 + 1, y1 = y0 + 1;
  bool vx0 = (x0 >= 0) && (x0 < W), vx1 = (x1 >= 0) && (x1 < W);
  bool vy0 = (y0 >= 0) && (y0 < H), vy1 = (y1 >= 0) && (y1 < H);
  float v00 = (vx0 && vy0) ? base[y0*W + x0] : 0.f;
  float v01 = (vx1 && vy0) ? base[y0*W + x1] : 0.f;
  float v10 = (vx0 && vy1) ? base[y1*W + x0] : 0.f;
  float v11 = (vx1 && vy1) ? base[y1*W + x1] : 0.f;
  return v00*(1.f-wx)*(1.f-wy) + v01*wx*(1.f-wy) + v10*(1.f-wx)*wy + v11*wx*wy;
}

// =========================================================================
// Kernel 1: per batch -> top2 maps -> uncertainty (bitwise-matching the
// reference's eager f32 op sequence) -> exact top-768 via radix select ->
// bitonic sort of 1024 -> points written into d_out
// =========================================================================
__global__ __launch_bounds__(1024) void k2_points(
    const float* __restrict__ coarse, const float* __restrict__ over_gen,
    const float* __restrict__ coverage, float* __restrict__ out)
{
  extern __shared__ char sm[];
  float* m1s = (float*)sm;                       // 4096 f
  float* m2s = m1s + 4096;                       // 4096 f
  ull*   keys = (ull*)(sm + 32768);              // 7168 u64
  ull*   sel  = (ull*)(sm + 32768 + 57344);      // 1024 u64
  unsigned* cum  = (unsigned*)(sm + 98304);      // 256
  unsigned* misc = cum + 256;                    // [0]=krem [1]=digit [2]=below [3]=cnt
  ull* s_pfx = (ull*)(misc + 4);

  const int b = blockIdx.x, tid = threadIdx.x;
  const float NEG_INF = __int_as_float(0xff800000);

  const float* cb = coarse + (size_t)b*7*4096;
  for (int l = tid; l < 4096; l += 1024){
    float m1 = NEG_INF, m2 = NEG_INF;
    #pragma unroll
    for (int c = 0; c < 7; c++){
      float v = cb[c*4096 + l];
      if (v > m1){ m2 = m1; m1 = v; } else if (v > m2) m2 = v;
    }
    m1s[l] = m1; m2s[l] = m2;
  }
  if (tid == 0){ *s_pfx = 0ull; misc[0] = NIMP; misc[3] = 0; }
  __syncthreads();

  const float* og = over_gen + (size_t)b*NOVER*2;
  for (int t = 0; t < 7; t++){
    int i = tid + t*1024;
    float px = og[i*2], py = og[i*2 + 1];
    float gx = __fsub_rn(__fmul_rn(2.f, px), 1.f);
    float gy = __fsub_rn(__fmul_rn(2.f, py), 1.f);
    float x  = __fmul_rn(__fsub_rn(__fmul_rn(__fadd_rn(gx, 1.f), 64.f), 1.f), 0.5f);
    float y  = __fmul_rn(__fsub_rn(__fmul_rn(__fadd_rn(gy, 1.f), 64.f), 1.f), 0.5f);
    float x0f = floorf(x), y0f = floorf(y);
    float wx = __fsub_rn(x, x0f), wy = __fsub_rn(y, y0f);
    float omx = __fsub_rn(1.f, wx), omy = __fsub_rn(1.f, wy);
    float x1f = __fadd_rn(x0f, 1.f), y1f = __fadd_rn(y0f, 1.f);
    bool vx0 = (x0f >= 0.f) && (x0f <= 63.f);
    bool vx1 = (x1f >= 0.f) && (x1f <= 63.f);
    bool vy0 = (y0f >= 0.f) && (y0f <= 63.f);
    bool vy1 = (y1f >= 0.f) && (y1f <= 63.f);
    int ix0 = min(max((int)x0f, 0), 63), iy0 = min(max((int)y0f, 0), 63);
    int ix1 = min(max((int)x1f, 0), 63), iy1 = min(max((int)y1f, 0), 63);
    int o00 = iy0*64 + ix0, o01 = iy0*64 + ix1, o10 = iy1*64 + ix0, o11 = iy1*64 + ix1;
    float a00 = (vx0 && vy0) ? m1s[o00] : 0.f;
    float a01 = (vx1 && vy0) ? m1s[o01] : 0.f;
    float a10 = (vx0 && vy1) ? m1s[o10] : 0.f;
    float a11 = (vx1 && vy1) ? m1s[o11] : 0.f;
    float b00 = (vx0 && vy0) ? m2s[o00] : 0.f;
    float b01 = (vx1 && vy0) ? m2s[o01] : 0.f;
    float b10 = (vx0 && vy1) ? m2s[o10] : 0.f;
    float b11 = (vx1 && vy1) ? m2s[o11] : 0.f;
    float s0 = __fadd_rn(__fadd_rn(__fadd_rn(
                 __fmul_rn(__fmul_rn(a00, omx), omy),
                 __fmul_rn(__fmul_rn(a01, wx ), omy)),
                 __fmul_rn(__fmul_rn(a10, omx), wy )),
                 __fmul_rn(__fmul_rn(a11, wx ), wy ));
    float s1 = __fadd_rn(__fadd_rn(__fadd_rn(
                 __fmul_rn(__fmul_rn(b00, omx), omy),
                 __fmul_rn(__fmul_rn(b01, wx ), omy)),
                 __fmul_rn(__fmul_rn(b10, omx), wy )),
                 __fmul_rn(__fmul_rn(b11, wx ), wy ));
    float unc = __fsub_rn(s1, s0);
    unsigned u = __float_as_uint(unc);
    unsigned mo = (u & 0x80000000u) ? ~u : (u | 0x80000000u);
    unsigned kv = ~mo;                         // ascending kv == descending unc
    keys[i] = ((ull)kv << 13) | (unsigned)i;   // tie-break: ascending index
  }
  __syncthreads();

  // radix select: 768th-smallest 45-bit key
  for (int r = 0; r < 6; r++){
    if (tid < 256) cum[tid] = 0;
    __syncthreads();
    ull pfx = *s_pfx; unsigned krem = misc[0];
    int shift = 40 - 8*r;
    for (int t = 0; t < 7; t++){
      ull key = keys[tid + t*1024];
      if ((key >> (shift + 8)) == pfx)
        atomicAdd(&cum[(unsigned)(key >> shift) & 255u], 1u);
    }
    __syncthreads();
    for (int off = 1; off < 256; off <<= 1){
      unsigned v = 0;
      if (tid < 256 && tid >= off) v = cum[tid - off];
      __syncthreads();
      if (tid < 256) cum[tid] += v;
      __syncthreads();
    }
    if (tid < 256){
      unsigned le = cum[tid];
      unsigned lt = tid ? cum[tid - 1] : 0u;
      if (le >= krem && lt < krem){ misc[1] = tid; misc[2] = lt; }
    }
    __syncthreads();
    if (tid == 0){ *s_pfx = (*s_pfx << 8) | (ull)misc[1]; misc[0] -= misc[2]; }
    __syncthreads();
  }
  ull T = *s_pfx;

  for (int t = 0; t < 7; t++){
    ull key = keys[tid + t*1024];
    if (key <= T){
      unsigned pos = atomicAdd(&misc[3], 1u);
      if (pos < 1024) sel[pos] = key;
    }
  }
  __syncthreads();
  if (tid >= NIMP) sel[tid] = ~0ull;
  __syncthreads();
  for (int k = 2; k <= 1024; k <<= 1){
    for (int j = k >> 1; j > 0; j >>= 1){
      int ixj = tid ^ j;
      if (ixj > tid){
        ull a = sel[tid], bb = sel[ixj];
        bool up = ((tid & k) == 0);
        if ((a > bb) == up){ sel[tid] = bb; sel[ixj] = a; }
      }
      __syncthreads();
    }
  }

  float px, py;
  if (tid < NIMP){
    int idx = (int)(sel[tid] & 0x1FFFu);
    px = og[idx*2]; py = og[idx*2 + 1];
  } else {
    int j = tid - NIMP;
    px = coverage[((size_t)b*NCOV + j)*2];
    py = coverage[((size_t)b*NCOV + j)*2 + 1];
  }
  float* op = out + REND_ELEMS + ((size_t)b*NP + tid)*2;
  op[0] = px; op[1] = py;
}

// =========================================================================
// Kernel 2 (gather): one thread per (b, pt, c). Zero smem, huge grid ->
// maximum memory-level parallelism for the scattered bilinear reads.
// Writes g_feat[b][pt][c] coalesced.
// =========================================================================
__global__ __launch_bounds__(256) void k_gather(
    const float* __restrict__ coarse, const float* __restrict__ fine,
    const float* __restrict__ out)
{
  int i = blockIdx.x*256 + threadIdx.x;
  if (i >= GITEMS) return;
  int b  = i / (NP*NCH);
  int r  = i - b*(NP*NCH);
  int pt = r / NCH;
  int c  = r - pt*NCH;

  const float* p = out + REND_ELEMS + ((size_t)b*NP + pt)*2;
  float px = __ldg(p), py = __ldg(p + 1);

  float val;
  if (c < 7) val = bil(coarse + ((size_t)b*7 + c)*4096, 64, 64, px, py);
  else       val = bil(fine + ((size_t)b*128 + (c - 7))*65536, 256, 256, px, py);
  g_feat[((size_t)b*NP + pt)*FPITCH + c] = val;
}

// =========================================================================
// Kernel 3 (MLP): feat from g_feat (streaming), 135->256 relu ->7.
// 128 blocks (b, chunk of 128 points), 512 threads, f32x2 register tiles.
// =========================================================================
__global__ __launch_bounds__(512) void k3_head(
    const float* __restrict__ w1, const float* __restrict__ b1,
    const float* __restrict__ w2, const float* __restrict__ b2,
    float* __restrict__ out)
{
  extern __shared__ float sf[];
  float* fs  = sf;                    // 128*136
  float* wsh = fs + 128*136;          // 16*256
  float* w2s = wsh + 4096;            // 256*7
  float* hs  = w2s + 1792;            // 128*258

  const int b = blockIdx.y, chunk = blockIdx.x;
  const int tid = threadIdx.x;
  const int pbase = chunk*128;

  // streaming copy of the feat tile + w2
  const float* gsrc = g_feat + ((size_t)b*NP + pbase)*FPITCH;
  for (int i = tid; i < 128*FPITCH; i += 512) fs[i] = gsrc[i];
  for (int i = tid; i < 1792; i += 512) w2s[i] = w2[i];

  // GEMM1: h = relu(feat @ w1 + b1), packed f32x2, 8pt x 8col per thread.
  const int colg = tid & 31, ptg = tid >> 5;
  const int p0 = ptg*8;
  ull acc[8][4];
  {
    ull binit[4];
    #pragma unroll
    for (int q = 0; q < 4; q++){
      int c0 = 2*colg + 64*q;
      binit[q] = pack2(b1[c0], b1[c0 + 1]);
    }
    #pragma unroll
    for (int p = 0; p < 8; p++)
      #pragma unroll
      for (int q = 0; q < 4; q++) acc[p][q] = binit[q];
  }
  for (int k0 = 0; k0 < 135; k0 += 16){
    int kc = min(16, 135 - k0);
    __syncthreads();                               // covers copy->read too
    for (int i = tid; i < kc*256; i += 512) wsh[i] = w1[k0*256 + i];
    __syncthreads();
    for (int r = 0; r < kc; r++){
      const ull* wrow = (const ull*)(wsh + r*256);
      ull wv0 = wrow[colg], wv1 = wrow[colg + 32], wv2 = wrow[colg + 64], wv3 = wrow[colg + 96];
      const float* fcol = fs + (k0 + r);
      #pragma unroll
      for (int p = 0; p < 8; p++){
        float fv = fcol[(p0 + p)*FPITCH];
        ull ff = pack2(fv, fv);
        acc[p][0] = fma2(ff, wv0, acc[p][0]);
        acc[p][1] = fma2(ff, wv1, acc[p][1]);
        acc[p][2] = fma2(ff, wv2, acc[p][2]);
        acc[p][3] = fma2(ff, wv3, acc[p][3]);
      }
    }
  }

  // relu -> hs
  #pragma unroll
  for (int p = 0; p < 8; p++){
    #pragma unroll
    for (int q = 0; q < 4; q++){
      float lo, hi; unpack2(acc[p][q], lo, hi);
      int c0 = 2*colg + 64*q;
      hs[(p0 + p)*258 + c0]     = fmaxf(lo, 0.f);
      hs[(p0 + p)*258 + c0 + 1] = fmaxf(hi, 0.f);
    }
  }
  __syncthreads();

  // GEMM2: rend[b][cls][n] = h @ w2 + b2
  for (int t = tid; t < 896; t += 512){
    int pt = t / 7, cls = t - pt*7;
    const float* hrow = hs + pt*258;
    float s = b2[cls];
    #pragma unroll 8
    for (int k = 0; k < 256; k++) s = fmaf(hrow[k], w2s[k*7 + cls], s);
    out[((size_t)b*7 + cls)*NP + pbase + pt] = s;
  }
}

// =========================================================================
extern "C" void kernel_launch(void* const* d_in, const int* in_sizes, int n_in,
                              void* d_out, int out_size){
  const float *fine = nullptr, *coarse = nullptr, *w1 = nullptr, *b1 = nullptr,
              *w2 = nullptr, *b2 = nullptr, *og = nullptr, *cov = nullptr;
  for (int i = 0; i < n_in; i++){
    switch (in_sizes[i]){
      case 134217728: fine   = (const float*)d_in[i]; break;
      case 458752:    coarse = (const float*)d_in[i]; break;
      case 34560:     w1     = (const float*)d_in[i]; break;
      case 256:       b1     = (const float*)d_in[i]; break;
      case 1792:      w2     = (const float*)d_in[i]; break;
      case 7:         b2     = (const float*)d_in[i]; break;
      case 229376:    og     = (const float*)d_in[i]; break;
      case 8192:      cov    = (const float*)d_in[i]; break;
      default: break;
    }
  }
  float* out = (float*)d_out;

  const size_t sm2 = 100352;
  const size_t sm3 = (size_t)(128*FPITCH + 4096 + 1792 + 128*258)*sizeof(float); // ~225KB
  cudaFuncSetAttribute(k2_points, cudaFuncAttributeMaxDynamicSharedMemorySize, (int)sm2);
  cudaFuncSetAttribute(k3_head,   cudaFuncAttributeMaxDynamicSharedMemorySize, (int)sm3);

  k2_points<<<NB, 1024, sm2>>>(coarse, og, cov, out);
  k_gather<<<(GITEMS + 255)/256, 256>>>(coarse, fine, out);
  k3_head<<<dim3(8, NB), 512, sm3>>>(w1, b1, w2, b2, out);
}